// round 12
// baseline (speedup 1.0000x reference)
#include <cuda_runtime.h>
#include <cstdint>

#define WW 640
#define HH 480
#define HWPX (WW*HH)           // 307200
#define NB 8
#define NG 368640              // B*H*W*0.15
#define NTOT (NB*NG)           // 2949120
#define H2_BLOCKS 720          // pass2: 720*256 threads * 16 ushorts = NTOT

// Scratch (static __device__ — no allocation allowed)
static __device__ __align__(16) float g_gt_t[HWPX*NB];   // [pix][b]
static __device__ __align__(16) float g_pd_t[HWPX*NB];
static __device__ __align__(16) unsigned short g_L16[NTOT];
static __device__ unsigned g_cnt[4096];
static __device__ float    g_sumb[4096];
static __device__ unsigned g_c2[16];
static __device__ float    g_s2[16];
static __device__ double g_Shi;
static __device__ unsigned g_k, g_b1, g_m1;
static __device__ unsigned g_ticket, g_ticket2;

__device__ __forceinline__ float comp4(const float4& v, int p) {
    return p == 0 ? v.x : (p == 1 ? v.y : (p == 2 ? v.z : v.w));
}

// ---------------------------------------------------------------------------
// Fused: transpose [B,H,W] -> [H*W, B] (4 pixels/thread, float4 both ways)
// + zero all selection scratch.
__global__ void __launch_bounds__(256) k_init(const float* __restrict__ gt,
                                              const float* __restrict__ pd) {
    int t = blockIdx.x*blockDim.x + threadIdx.x;   // HWPX/4 = 76800 threads
    if (t < 4096) { g_cnt[t] = 0u; g_sumb[t] = 0.0f; }
    if (t < 16)   { g_c2[t] = 0u; g_s2[t] = 0.0f; }
    if (t == 0)   { g_Shi = 0.0; g_ticket = 0u; g_ticket2 = 0u; }

    float4 a[NB];
#pragma unroll
    for (int b = 0; b < NB; b++)
        a[b] = __ldg(reinterpret_cast<const float4*>(gt + (size_t)b*HWPX) + t);
#pragma unroll
    for (int p = 0; p < 4; p++) {
        float4* o = reinterpret_cast<float4*>(g_gt_t + (size_t)(t*4 + p)*NB);
        o[0] = make_float4(comp4(a[0],p), comp4(a[1],p), comp4(a[2],p), comp4(a[3],p));
        o[1] = make_float4(comp4(a[4],p), comp4(a[5],p), comp4(a[6],p), comp4(a[7],p));
    }
#pragma unroll
    for (int b = 0; b < NB; b++)
        a[b] = __ldg(reinterpret_cast<const float4*>(pd + (size_t)b*HWPX) + t);
#pragma unroll
    for (int p = 0; p < 4; p++) {
        float4* o = reinterpret_cast<float4*>(g_pd_t + (size_t)(t*4 + p)*NB);
        o[0] = make_float4(comp4(a[0],p), comp4(a[1],p), comp4(a[2],p), comp4(a[3],p));
        o[1] = make_float4(comp4(a[4],p), comp4(a[5],p), comp4(a[6],p), comp4(a[7],p));
    }
}

// FMA-only rsqrt, 2 Newton steps (~4.5e-6 rel err; MUFU pipe stays empty)
__device__ __forceinline__ float fast_rsqrt_pos(float x) {
    float y = __uint_as_float(0x5f37599eu - (__float_as_uint(x) >> 1));
    float xh = 0.5f * x;
    y = y * (1.5f - xh*y*y);
    y = y * (1.5f - xh*y*y);
    return y;
}

// One thread per (group, batch). smem 12-bit histogram of (count, float sum).
// Stores top-16 float bits of L (0xFFFF = dropped). Last-finishing block
// resolves (k, b1, m1) and the EXACT sum above bin b1.
__global__ void __launch_bounds__(256) k_compute(
        const int* __restrict__ p1x, const int* __restrict__ p1y,
        const int* __restrict__ p2x, const int* __restrict__ p2y,
        const int* __restrict__ p3x, const int* __restrict__ p3y) {
    __shared__ unsigned scnt[4096];
    __shared__ float    ssum[4096];
    for (int i = threadIdx.x; i < 4096; i += blockDim.x) { scnt[i] = 0u; ssum[i] = 0.0f; }
    __syncthreads();

    int tid = blockIdx.x*blockDim.x + threadIdx.x;   // NTOT threads exactly
    int g = tid >> 3;
    int b = tid & 7;

    const float INV_F = 1.0f/519.0f;
    int x1 = p1x[g], y1 = p1y[g];
    int x2 = p2x[g], y2 = p2y[g];
    int x3 = p3x[g], y3 = p3y[g];
    float u1 = ((float)x1 - 320.0f)*INV_F, v1 = ((float)y1 - 240.0f)*INV_F;
    float u2 = ((float)x2 - 320.0f)*INV_F, v2 = ((float)y2 - 240.0f)*INV_F;
    float u3 = ((float)x3 - 320.0f)*INV_F, v3 = ((float)y3 - 240.0f)*INV_F;
    int o1 = (y1*WW + x1)*NB + b;
    int o2 = (y2*WW + x2)*NB + b;
    int o3 = (y3*WW + x3)*NB + b;

    float d1 = g_gt_t[o1], d2 = g_gt_t[o2], d3 = g_gt_t[o3];
    float q1 = g_pd_t[o1], q2 = g_pd_t[o2], q3 = g_pd_t[o3];

    // GT 3D points
    float A1x = u1*fabsf(d1), A1y = v1*fabsf(d1), A1z = d1;
    float A2x = u2*fabsf(d2), A2y = v2*fabsf(d2), A2z = d2;
    float A3x = u3*fabsf(d3), A3y = v3*fabsf(d3), A3z = d3;
    float ax = A2x-A1x, ay = A2y-A1y, az = A2z-A1z;     // d12
    float bx = A3x-A1x, by = A3y-A1y, bz = A3z-A1z;     // d13
    float cx = bx-ax,   cy = by-ay,   cz = bz-az;       // d23 = d13-d12
    float e11 = ax*ax+ay*ay+az*az;
    float e22 = bx*bx+by*by+bz*bz;
    float e12 = ax*bx+ay*by+az*bz;
    float e13 = e12 - e11;                              // a·(b-a)
    float e23 = e22 - e12;                              // b·(b-a)
    float e33 = e11 + e22 - 2.0f*e12;                   // |b-a|^2
    const float DIAG_T = 6.518797e-8f;   // 0.867e-8/0.133
    const float C2 = 0.751689f;          // 0.867^2
    int cnt = 0;
    cnt += (e11 > DIAG_T) ? 1 : 0;
    cnt += (e22 > DIAG_T) ? 1 : 0;
    cnt += (e33 > DIAG_T) ? 1 : 0;
    cnt += (e12*e12 > C2*e11*e22) ? 2 : 0;
    cnt += (e13*e13 > C2*e11*e33) ? 2 : 0;
    cnt += (e23*e23 > C2*e22*e33) ? 2 : 0;
    bool mcos = cnt > 3;
    bool mx = (fabsf(ax) < 0.01f) | (fabsf(bx) < 0.01f) | (fabsf(cx) < 0.01f);
    bool my = (fabsf(ay) < 0.01f) | (fabsf(by) < 0.01f) | (fabsf(cy) < 0.01f);
    bool mz = (fabsf(az) < 0.01f) | (fabsf(bz) < 0.01f) | (fabsf(cz) < 0.01f);
    bool keep = !((mx & my & mz) | mcos);

    // Pred 3D points (replicating the reference's zmask coord/point mixup)
    float B1x = u1*fabsf(q1), B1y = v1*fabsf(q1), B1z = q1;
    float B2x = u2*fabsf(q2), B2y = v2*fabsf(q2), B2z = q2;
    float B3x = u3*fabsf(q3), B3y = v3*fabsf(q3), B3z = q3;
    if (q1 == 0.0f) { B1x = 1e-4f; B2x = 1e-4f; B3x = 1e-4f; }
    if (q2 == 0.0f) { B1y = 1e-4f; B2y = 1e-4f; B3y = 1e-4f; }
    if (q3 == 0.0f) { B1z = 1e-4f; B2z = 1e-4f; B3z = 1e-4f; }
    float px_ = B2x-B1x, py_ = B2y-B1y, pz_ = B2z-B1z;
    float qx_ = B3x-B1x, qy_ = B3y-B1y, qz_ = B3z-B1z;

    float gnx = ay*bz - az*by;
    float gny = az*bx - ax*bz;
    float gnz = ax*by - ay*bx;
    float dnx = py_*qz_ - pz_*qy_;
    float dny = pz_*qx_ - px_*qz_;
    float dnz = px_*qy_ - py_*qx_;
    float gg = gnx*gnx + gny*gny + gnz*gnz;
    float dd = dnx*dnx + dny*dny + dnz*dnz;
    float rg, rd;
    if (gg >= 1.1754944e-38f)      rg = fast_rsqrt_pos(gg);
    else if (gg > 0.0f)            rg = 1.0f/sqrtf(gg);   // cold path
    else                           rg = 0.0f;             // ref: 0 / 0.01
    if (dd >= 1.1754944e-38f)      rd = fast_rsqrt_pos(dd);
    else if (dd > 0.0f)            rd = 1.0f/sqrtf(dd);
    else                           rd = 0.0f;
    float L = fabsf(gnx*rg - dnx*rd) + fabsf(gny*rg - dny*rd) + fabsf(gnz*rg - dnz*rd);

    unsigned bits = __float_as_uint(L);
    g_L16[tid] = keep ? (unsigned short)(bits >> 16) : (unsigned short)0xFFFFu;
    if (keep) {
        unsigned bin = bits >> 20;               // 12-bit: sign+exp+3 mantissa
        atomicAdd(&scnt[bin], 1u);
        atomicAdd(&ssum[bin], L);
    }
    __syncthreads();
    for (int i = threadIdx.x; i < 4096; i += blockDim.x) {
        unsigned v = scnt[i];
        if (v) { atomicAdd(&g_cnt[i], v); atomicAdd(&g_sumb[i], ssum[i]); }
    }

    // ---- last-finishing block: resolve (k, b1, m1) + exact sum above b1 ----
    __shared__ unsigned s_last;
    __threadfence();
    __syncthreads();
    if (threadIdx.x == 0) s_last = atomicAdd(&g_ticket, 1u);
    __syncthreads();
    if (s_last != gridDim.x - 1) return;
    __threadfence();   // acquire: see all blocks' flushes

    __shared__ unsigned ts[256];
    __shared__ unsigned ws[8];
    __shared__ unsigned s_b1;
    __shared__ double dred[8];
    int t = threadIdx.x;
    unsigned s = 0;
#pragma unroll
    for (int i = 0; i < 16; i++) {
        unsigned v = g_cnt[t*16 + i];
        scnt[t*16 + i] = v;
        s += v;
    }
    ts[t] = s;
#pragma unroll
    for (int o = 16; o; o >>= 1) s += __shfl_down_sync(0xFFFFFFFFu, s, o);
    if ((t & 31) == 0) ws[t >> 5] = s;
    __syncthreads();
    if (t == 0) {
        unsigned n = 0;
        for (int i = 0; i < 8; i++) n += ws[i];
        unsigned k = n - (n >> 2);
        g_k = k;
        if (k == 0) { g_b1 = 0xFFFFFFFFu; g_m1 = 0u; s_b1 = 0xFFFFFFFFu; }
        else {
            unsigned above = 0;
            int w = 7;
            while (above + ws[w] < k) { above += ws[w]; w--; }
            int th = w*32 + 31;
            while (above + ts[th] < k) { above += ts[th]; th--; }
            int bin = th*16 + 15;
            while (above + scnt[bin] < k) { above += scnt[bin]; bin--; }
            g_b1 = (unsigned)bin;
            g_m1 = k - above;
            s_b1 = (unsigned)bin;
        }
    }
    __syncthreads();
    unsigned b1r = s_b1;
    if (b1r == 0xFFFFFFFFu) return;     // g_Shi stays 0
    double loc = 0.0;
#pragma unroll
    for (int i = 0; i < 16; i++) {
        int idx = t*16 + i;
        if ((unsigned)idx > b1r && scnt[idx]) loc += (double)g_sumb[idx];
    }
#pragma unroll
    for (int o = 16; o; o >>= 1) loc += __shfl_down_sync(0xFFFFFFFFu, loc, o);
    if ((t & 31) == 0) dred[t >> 5] = loc;
    __syncthreads();
    if (t == 0) {
        double tot = 0.0;
        for (int i = 0; i < 8; i++) tot += dred[i];
        g_Shi = tot;
    }
}

// Pass 2: scan g_L16 (5.9 MB), refine the 16 sub-bins of boundary bin b1.
// Last-finishing block computes the final loss.
__global__ void __launch_bounds__(256) k_pass2(float* out) {
    __shared__ unsigned c16[16];
    __shared__ float    s16[16];
    if (threadIdx.x < 16) { c16[threadIdx.x] = 0u; s16[threadIdx.x] = 0.0f; }
    __syncthreads();
    unsigned b1 = g_b1;
    int t = blockIdx.x*blockDim.x + threadIdx.x;   // H2_BLOCKS*256 threads
    const uint4* P = reinterpret_cast<const uint4*>(g_L16);
#pragma unroll
    for (int j = 0; j < 2; j++) {
        uint4 u = P[t + j*(H2_BLOCKS*256)];
        unsigned wv[4] = {u.x, u.y, u.z, u.w};
#pragma unroll
        for (int e = 0; e < 4; e++) {
            unsigned h0 = wv[e] & 0xFFFFu;
            unsigned h1 = wv[e] >> 16;
            if ((h0 >> 4) == b1) {
                atomicAdd(&c16[h0 & 15u], 1u);
                atomicAdd(&s16[h0 & 15u], __uint_as_float(h0 << 16));
            }
            if ((h1 >> 4) == b1) {
                atomicAdd(&c16[h1 & 15u], 1u);
                atomicAdd(&s16[h1 & 15u], __uint_as_float(h1 << 16));
            }
        }
    }
    __syncthreads();
    if (threadIdx.x < 16) {
        unsigned c = c16[threadIdx.x];
        if (c) { atomicAdd(&g_c2[threadIdx.x], c); atomicAdd(&g_s2[threadIdx.x], s16[threadIdx.x]); }
    }

    // ---- last-finishing block: final resolution ----
    __shared__ unsigned s_last;
    __threadfence();
    __syncthreads();
    if (threadIdx.x == 0) s_last = atomicAdd(&g_ticket2, 1u);
    __syncthreads();
    if (s_last != gridDim.x - 1) return;

    if (threadIdx.x == 0) {
        __threadfence();   // acquire: see all blocks' g_c2/g_s2
        unsigned k = g_k;
        if (k == 0u) { out[0] = 0.0f; return; }
        unsigned m1 = g_m1;
        unsigned above = 0;
        int sbin = 15;
        while (above + g_c2[sbin] < m1) { above += g_c2[sbin]; sbin--; }
        unsigned m2 = m1 - above;
        unsigned cs = g_c2[sbin];
        double tot = g_Shi;
        for (int i = sbin + 1; i < 16; i++) tot += (double)g_s2[i];
        tot += (double)g_s2[sbin] * ((double)m2 / (double)cs);
        out[0] = (float)(tot / (double)k);
    }
}

// ---------------------------------------------------------------------------
extern "C" void kernel_launch(void* const* d_in, const int* in_sizes, int n_in,
                              void* d_out, int out_size) {
    const float* gt = (const float*)d_in[0];
    const float* pd = (const float*)d_in[1];
    const int* p1x = (const int*)d_in[2];
    const int* p1y = (const int*)d_in[3];
    const int* p2x = (const int*)d_in[4];
    const int* p2y = (const int*)d_in[5];
    const int* p3x = (const int*)d_in[6];
    const int* p3y = (const int*)d_in[7];
    float* out = (float*)d_out;

    k_init<<<HWPX/4/256, 256>>>(gt, pd);
    k_compute<<<NTOT/256, 256>>>(p1x, p1y, p2x, p2y, p3x, p3y);
    k_pass2<<<H2_BLOCKS, 256>>>(out);
}

// round 14
// speedup vs baseline: 1.4866x; 1.4866x over previous
#include <cuda_runtime.h>
#include <cstdint>

#define WW 640
#define HH 480
#define HWPX (WW*HH)           // 307200
#define NB 8
#define NG 368640              // B*H*W*0.15
#define NTOT (NB*NG)           // 2949120
#define H2_BLOCKS 720          // pass2: 720*256 threads * 2 uint4 * 8 ushorts = NTOT

// Scratch (static __device__ — no allocation allowed)
static __device__ __align__(16) float g_gt_t[HWPX*NB];   // [pix][b]
static __device__ __align__(16) float g_pd_t[HWPX*NB];
static __device__ __align__(16) unsigned short g_L16[NTOT];
static __device__ unsigned g_cnt[4096];
static __device__ unsigned g_c2[16];
static __device__ float    g_s2[16];
static __device__ double g_Shi;
static __device__ unsigned g_k, g_b1, g_m1;
static __device__ unsigned g_ticket, g_ticket2;

// ---------------------------------------------------------------------------
// Fused: transpose [B,H,W] -> [H*W, B] (1 pixel/thread — proven 10.4us form)
// + zero all selection scratch.
__global__ void k_init(const float* __restrict__ gt, const float* __restrict__ pd) {
    int pix = blockIdx.x*blockDim.x + threadIdx.x;
    if (pix < 4096) g_cnt[pix] = 0u;
    if (pix < 16)   { g_c2[pix] = 0u; g_s2[pix] = 0.0f; }
    if (pix == 0)   { g_Shi = 0.0; g_ticket = 0u; g_ticket2 = 0u; }
    if (pix >= HWPX) return;
    float v[NB], w[NB];
#pragma unroll
    for (int b = 0; b < NB; b++) {
        v[b] = __ldg(gt + b*HWPX + pix);
        w[b] = __ldg(pd + b*HWPX + pix);
    }
    float4* o = reinterpret_cast<float4*>(g_gt_t + (size_t)pix*NB);
    o[0] = make_float4(v[0], v[1], v[2], v[3]);
    o[1] = make_float4(v[4], v[5], v[6], v[7]);
    float4* p = reinterpret_cast<float4*>(g_pd_t + (size_t)pix*NB);
    p[0] = make_float4(w[0], w[1], w[2], w[3]);
    p[1] = make_float4(w[4], w[5], w[6], w[7]);
}

// FMA-only rsqrt, 2 Newton steps (~4.5e-6 rel err; MUFU pipe stays empty)
__device__ __forceinline__ float fast_rsqrt_pos(float x) {
    float y = __uint_as_float(0x5f37599eu - (__float_as_uint(x) >> 1));
    float xh = 0.5f * x;
    y = y * (1.5f - xh*y*y);
    y = y * (1.5f - xh*y*y);
    return y;
}

// One thread per (group, batch). Stores round-to-nearest-even 16-bit L
// (0xFFFF = dropped). smem 12-bit histogram, warp-aggregated counts only.
// Last-finishing block resolves (k, b1, m1).
__global__ void __launch_bounds__(256) k_compute(
        const int* __restrict__ p1x, const int* __restrict__ p1y,
        const int* __restrict__ p2x, const int* __restrict__ p2y,
        const int* __restrict__ p3x, const int* __restrict__ p3y) {
    __shared__ unsigned sh[4096];
    for (int i = threadIdx.x; i < 4096; i += blockDim.x) sh[i] = 0u;
    __syncthreads();

    int tid = blockIdx.x*blockDim.x + threadIdx.x;   // NTOT threads exactly
    int g = tid >> 3;
    int b = tid & 7;

    const float INV_F = 1.0f/519.0f;
    int x1 = p1x[g], y1 = p1y[g];
    int x2 = p2x[g], y2 = p2y[g];
    int x3 = p3x[g], y3 = p3y[g];
    float u1 = ((float)x1 - 320.0f)*INV_F, v1 = ((float)y1 - 240.0f)*INV_F;
    float u2 = ((float)x2 - 320.0f)*INV_F, v2 = ((float)y2 - 240.0f)*INV_F;
    float u3 = ((float)x3 - 320.0f)*INV_F, v3 = ((float)y3 - 240.0f)*INV_F;
    int o1 = (y1*WW + x1)*NB + b;
    int o2 = (y2*WW + x2)*NB + b;
    int o3 = (y3*WW + x3)*NB + b;

    float d1 = g_gt_t[o1], d2 = g_gt_t[o2], d3 = g_gt_t[o3];
    float q1 = g_pd_t[o1], q2 = g_pd_t[o2], q3 = g_pd_t[o3];

    // GT 3D points
    float A1x = u1*fabsf(d1), A1y = v1*fabsf(d1), A1z = d1;
    float A2x = u2*fabsf(d2), A2y = v2*fabsf(d2), A2z = d2;
    float A3x = u3*fabsf(d3), A3y = v3*fabsf(d3), A3z = d3;
    float ax = A2x-A1x, ay = A2y-A1y, az = A2z-A1z;     // d12
    float bx = A3x-A1x, by = A3y-A1y, bz = A3z-A1z;     // d13
    float cx = bx-ax,   cy = by-ay,   cz = bz-az;       // d23 = d13-d12
    float e11 = ax*ax+ay*ay+az*az;
    float e22 = bx*bx+by*by+bz*bz;
    float e12 = ax*bx+ay*by+az*bz;
    float e13 = e12 - e11;                              // a·(b-a)
    float e23 = e22 - e12;                              // b·(b-a)
    float e33 = e11 + e22 - 2.0f*e12;                   // |b-a|^2
    const float DIAG_T = 6.518797e-8f;   // 0.867e-8/0.133
    const float C2 = 0.751689f;          // 0.867^2
    int cnt = 0;
    cnt += (e11 > DIAG_T) ? 1 : 0;
    cnt += (e22 > DIAG_T) ? 1 : 0;
    cnt += (e33 > DIAG_T) ? 1 : 0;
    cnt += (e12*e12 > C2*e11*e22) ? 2 : 0;
    cnt += (e13*e13 > C2*e11*e33) ? 2 : 0;
    cnt += (e23*e23 > C2*e22*e33) ? 2 : 0;
    bool mcos = cnt > 3;
    bool mx = (fabsf(ax) < 0.01f) | (fabsf(bx) < 0.01f) | (fabsf(cx) < 0.01f);
    bool my = (fabsf(ay) < 0.01f) | (fabsf(by) < 0.01f) | (fabsf(cy) < 0.01f);
    bool mz = (fabsf(az) < 0.01f) | (fabsf(bz) < 0.01f) | (fabsf(cz) < 0.01f);
    bool keep = !((mx & my & mz) | mcos);

    // Pred 3D points (replicating the reference's zmask coord/point mixup)
    float B1x = u1*fabsf(q1), B1y = v1*fabsf(q1), B1z = q1;
    float B2x = u2*fabsf(q2), B2y = v2*fabsf(q2), B2z = q2;
    float B3x = u3*fabsf(q3), B3y = v3*fabsf(q3), B3z = q3;
    if (q1 == 0.0f) { B1x = 1e-4f; B2x = 1e-4f; B3x = 1e-4f; }
    if (q2 == 0.0f) { B1y = 1e-4f; B2y = 1e-4f; B3y = 1e-4f; }
    if (q3 == 0.0f) { B1z = 1e-4f; B2z = 1e-4f; B3z = 1e-4f; }
    float px_ = B2x-B1x, py_ = B2y-B1y, pz_ = B2z-B1z;
    float qx_ = B3x-B1x, qy_ = B3y-B1y, qz_ = B3z-B1z;

    float gnx = ay*bz - az*by;
    float gny = az*bx - ax*bz;
    float gnz = ax*by - ay*bx;
    float dnx = py_*qz_ - pz_*qy_;
    float dny = pz_*qx_ - px_*qz_;
    float dnz = px_*qy_ - py_*qx_;
    float gg = gnx*gnx + gny*gny + gnz*gnz;
    float dd = dnx*dnx + dny*dny + dnz*dnz;
    float rg, rd;
    if (gg >= 1.1754944e-38f)      rg = fast_rsqrt_pos(gg);
    else if (gg > 0.0f)            rg = 1.0f/sqrtf(gg);   // cold path
    else                           rg = 0.0f;             // ref: 0 / 0.01
    if (dd >= 1.1754944e-38f)      rd = fast_rsqrt_pos(dd);
    else if (dd > 0.0f)            rd = 1.0f/sqrtf(dd);
    else                           rd = 0.0f;
    float L = fabsf(gnx*rg - dnx*rd) + fabsf(gny*rg - dny*rd) + fabsf(gnz*rg - dnz*rd);

    // round-to-nearest-even 16-bit representation (unbiased quantization)
    unsigned bits = __float_as_uint(L);
    unsigned u16 = (bits + 0x7FFFu + ((bits >> 16) & 1u)) >> 16;
    g_L16[tid] = keep ? (unsigned short)u16 : (unsigned short)0xFFFFu;
    if (keep) {
        unsigned bin = u16 >> 4;                   // 12-bit bin of quantized L
        unsigned am = __activemask();
        unsigned peers = __match_any_sync(am, bin);
        if ((threadIdx.x & 31) == (unsigned)(__ffs(peers) - 1))
            atomicAdd(&sh[bin], (unsigned)__popc(peers));
    }
    __syncthreads();
    for (int i = threadIdx.x; i < 4096; i += blockDim.x) {
        unsigned v = sh[i];
        if (v) atomicAdd(&g_cnt[i], v);
    }

    // ---- last-finishing block resolves (k, b1, m1) ----
    __shared__ unsigned s_last;
    __threadfence();
    __syncthreads();
    if (threadIdx.x == 0) s_last = atomicAdd(&g_ticket, 1u);
    __syncthreads();
    if (s_last != gridDim.x - 1) return;
    __threadfence();   // acquire: see all blocks' g_cnt flushes

    __shared__ unsigned ts[256];
    __shared__ unsigned ws[8];
    int t = threadIdx.x;
    unsigned s = 0;
#pragma unroll
    for (int i = 0; i < 16; i++) {
        unsigned v = g_cnt[t*16 + i];
        sh[t*16 + i] = v;
        s += v;
    }
    ts[t] = s;
#pragma unroll
    for (int o = 16; o; o >>= 1) s += __shfl_down_sync(0xFFFFFFFFu, s, o);
    if ((t & 31) == 0) ws[t >> 5] = s;
    __syncthreads();
    if (t == 0) {
        unsigned n = 0;
        for (int i = 0; i < 8; i++) n += ws[i];
        unsigned k = n - (n >> 2);
        g_k = k;
        if (k == 0) { g_b1 = 0xFFFFFFFFu; g_m1 = 0u; return; }
        unsigned above = 0;
        int w = 7;
        while (above + ws[w] < k) { above += ws[w]; w--; }
        int th = w*32 + 31;
        while (above + ts[th] < k) { above += ts[th]; th--; }
        int bin = th*16 + 15;
        while (above + sh[bin] < k) { above += sh[bin]; bin--; }
        g_b1 = (unsigned)bin;
        g_m1 = k - above;
    }
}

// Pass 2: scan g_L16 (5.9 MB). Values in bins > b1 -> shi; values in bin b1 ->
// 16 sub-bins (count + sum). Last-finishing block computes the final loss.
__global__ void __launch_bounds__(256) k_pass2(float* out) {
    __shared__ unsigned c16[16];
    __shared__ float    s16[16];
    if (threadIdx.x < 16) { c16[threadIdx.x] = 0u; s16[threadIdx.x] = 0.0f; }
    __syncthreads();
    unsigned b1 = g_b1;
    float shi = 0.f;
    int t = blockIdx.x*blockDim.x + threadIdx.x;   // H2_BLOCKS*256 threads
    const uint4* P = reinterpret_cast<const uint4*>(g_L16);
#pragma unroll
    for (int j = 0; j < 2; j++) {
        uint4 u = P[t + j*(H2_BLOCKS*256)];
        unsigned wv[4] = {u.x, u.y, u.z, u.w};
#pragma unroll
        for (int e = 0; e < 4; e++) {
            unsigned h0 = wv[e] & 0xFFFFu;
            unsigned h1 = wv[e] >> 16;
            unsigned bin0 = h0 >> 4, bin1 = h1 >> 4;
            if (h0 != 0xFFFFu) {
                if (bin0 > b1) shi += __uint_as_float(h0 << 16);
                else if (bin0 == b1) {
                    atomicAdd(&c16[h0 & 15u], 1u);
                    atomicAdd(&s16[h0 & 15u], __uint_as_float(h0 << 16));
                }
            }
            if (h1 != 0xFFFFu) {
                if (bin1 > b1) shi += __uint_as_float(h1 << 16);
                else if (bin1 == b1) {
                    atomicAdd(&c16[h1 & 15u], 1u);
                    atomicAdd(&s16[h1 & 15u], __uint_as_float(h1 << 16));
                }
            }
        }
    }
    // reduce shi (block) -> g_Shi
#pragma unroll
    for (int o = 16; o; o >>= 1) shi += __shfl_down_sync(0xFFFFFFFFu, shi, o);
    __shared__ float wsum[8];
    int wid = threadIdx.x >> 5;
    if ((threadIdx.x & 31) == 0) wsum[wid] = shi;
    __syncthreads();
    if (threadIdx.x == 0) {
        float a = 0.f;
        for (int i = 0; i < 8; i++) a += wsum[i];
        if (a != 0.f) atomicAdd(&g_Shi, (double)a);
    }
    if (threadIdx.x < 16) {
        unsigned c = c16[threadIdx.x];
        if (c) { atomicAdd(&g_c2[threadIdx.x], c); atomicAdd(&g_s2[threadIdx.x], s16[threadIdx.x]); }
    }

    // ---- last-finishing block: final resolution ----
    __shared__ unsigned s_last;
    __threadfence();
    __syncthreads();
    if (threadIdx.x == 0) s_last = atomicAdd(&g_ticket2, 1u);
    __syncthreads();
    if (s_last != gridDim.x - 1) return;

    if (threadIdx.x == 0) {
        __threadfence();   // acquire: see all blocks' g_c2/g_s2/g_Shi
        unsigned k = g_k;
        if (k == 0u) { out[0] = 0.0f; return; }
        unsigned m1 = g_m1;
        unsigned above = 0;
        int sbin = 15;
        while (above + g_c2[sbin] < m1) { above += g_c2[sbin]; sbin--; }
        unsigned m2 = m1 - above;
        unsigned cs = g_c2[sbin];
        double tot = g_Shi;
        for (int i = sbin + 1; i < 16; i++) tot += (double)g_s2[i];
        tot += (double)g_s2[sbin] * ((double)m2 / (double)cs);
        out[0] = (float)(tot / (double)k);
    }
}

// ---------------------------------------------------------------------------
extern "C" void kernel_launch(void* const* d_in, const int* in_sizes, int n_in,
                              void* d_out, int out_size) {
    const float* gt = (const float*)d_in[0];
    const float* pd = (const float*)d_in[1];
    const int* p1x = (const int*)d_in[2];
    const int* p1y = (const int*)d_in[3];
    const int* p2x = (const int*)d_in[4];
    const int* p2y = (const int*)d_in[5];
    const int* p3x = (const int*)d_in[6];
    const int* p3y = (const int*)d_in[7];
    float* out = (float*)d_out;

    k_init<<<(HWPX + 255)/256, 256>>>(gt, pd);
    k_compute<<<NTOT/256, 256>>>(p1x, p1y, p2x, p2y, p3x, p3y);
    k_pass2<<<H2_BLOCKS, 256>>>(out);
}